// round 11
// baseline (speedup 1.0000x reference)
#include <cuda_runtime.h>
#include <cuda_bf16.h>
#include <stdint.h>

#define NP   120000
#define INC  256
#define MIDC 64
#define OUTC 256
#define KNB  27
#define EPSV 1e-5f

// ---------------- scratch ----------------
__device__ float    g_y1[NP * MIDC];
__device__ float    g_h2[NP * MIDC];
__device__ unsigned g_hbt[NP * MIDC];
__device__ unsigned g_W3t[KNB * MIDC * MIDC];  // n-major: [k][n][kdim]
__device__ unsigned g_W2t[MIDC * OUTC];
__device__ float g_sum1[MIDC], g_ss1[MIDC], g_sc1[MIDC], g_sh1[MIDC];
__device__ float g_sum2[MIDC], g_ss2[MIDC], g_sc2[MIDC], g_sh2[MIDC];
__device__ float g_svec[MIDC];
__device__ float g_M[MIDC * MIDC];
__device__ float g_sc3[OUTC], g_sh3[OUTC];

__device__ __forceinline__ unsigned tf32_of(float f) {
    unsigned u;
    asm("cvt.rna.tf32.f32 %0, %1;" : "=r"(u) : "f"(f));
    return u;
}

__device__ __forceinline__ void mma_tf32(float* d, const unsigned* a, const unsigned* b) {
    asm volatile(
        "mma.sync.aligned.m16n8k8.row.col.f32.tf32.tf32.f32 "
        "{%0,%1,%2,%3}, {%4,%5,%6,%7}, {%8,%9}, {%0,%1,%2,%3};"
        : "+f"(d[0]), "+f"(d[1]), "+f"(d[2]), "+f"(d[3])
        : "r"(a[0]), "r"(a[1]), "r"(a[2]), "r"(a[3]), "r"(b[0]), "r"(b[1]));
}

__device__ __forceinline__ void ldsm_x4(unsigned& r0, unsigned& r1, unsigned& r2, unsigned& r3,
                                        uint32_t addr) {
    asm volatile("ldmatrix.sync.aligned.m8n8.x4.shared.b16 {%0,%1,%2,%3}, [%4];"
                 : "=r"(r0), "=r"(r1), "=r"(r2), "=r"(r3) : "r"(addr));
}

// ---------------- zero accumulators ----------------
__global__ void k_zero() {
    int i = blockIdx.x * blockDim.x + threadIdx.x;
    if (i < MIDC) {
        g_sum1[i] = 0.f; g_ss1[i] = 0.f;
        g_sum2[i] = 0.f; g_ss2[i] = 0.f;
        g_svec[i] = 0.f;
    }
    if (i < MIDC * MIDC) g_M[i] = 0.f;
}

// ---------------- weight conversions ----------------
// W3 -> tf32, TRANSPOSED to n-major: g_W3t[k][n][kdim]
__global__ void k_wcvt3(const float* __restrict__ W3) {
    int i = blockIdx.x * blockDim.x + threadIdx.x;  // 432*256 = 110592 exact
    int k  = i >> 12;
    int r  = i & 4095;
    int nc = r >> 6;
    int kr = r & 63;
    g_W3t[i] = tf32_of(W3[(k << 12) + (kr << 6) + nc]);
}
__global__ void k_wcvt2(const float* __restrict__ W2) {
    int i = blockIdx.x * blockDim.x + threadIdx.x;  // 64*256 exact
    g_W2t[i] = tf32_of(W2[i]);
}

// ---------------- GEMM1 (TF32 mma, R7 geometry): y1 = x @ W1, fused BN1 stats ----------
// 256 threads, 8 warps: 2 row-groups(48) x 4 col-groups(16)
__global__ void __launch_bounds__(256) k_gemm1(const float* __restrict__ x,
                                               const float* __restrict__ W1) {
    __shared__ unsigned As[96][68];
    __shared__ unsigned Bs[64][72];
    __shared__ float s_sum[MIDC], s_ss[MIDC];

    int t = threadIdx.x;
    if (t < MIDC) { s_sum[t] = 0.f; s_ss[t] = 0.f; }

    int rb = blockIdx.x * 96;
    int lane = t & 31, w = t >> 5;
    int wr = (w & 1) * 48;
    int wc = (w >> 1) * 16;
    int f = t & 15;
    int rbase = t >> 4;
    int qr = lane >> 2, qk = lane & 3;

    float acc[3][2][4] = {};

    for (int k0 = 0; k0 < INC; k0 += 64) {
        __syncthreads();
        #pragma unroll
        for (int j = 0; j < 4; j++) {
            int c = rbase + 16 * j;
            float4 v = *(const float4*)&W1[(size_t)(k0 + c) * MIDC + 4 * f];
            Bs[c][4 * f + 0] = tf32_of(v.x);
            Bs[c][4 * f + 1] = tf32_of(v.y);
            Bs[c][4 * f + 2] = tf32_of(v.z);
            Bs[c][4 * f + 3] = tf32_of(v.w);
        }
        #pragma unroll
        for (int j = 0; j < 6; j++) {
            int r = rbase + 16 * j;
            float4 v = *(const float4*)&x[(size_t)(rb + r) * INC + k0 + 4 * f];
            As[r][4 * f + 0] = tf32_of(v.x);
            As[r][4 * f + 1] = tf32_of(v.y);
            As[r][4 * f + 2] = tf32_of(v.z);
            As[r][4 * f + 3] = tf32_of(v.w);
        }
        __syncthreads();
        #pragma unroll
        for (int kk = 0; kk < 64; kk += 8) {
            unsigned b[2][2];
            #pragma unroll
            for (int nt = 0; nt < 2; nt++) {
                int col = wc + nt * 8 + qr;
                b[nt][0] = Bs[kk + qk][col];
                b[nt][1] = Bs[kk + qk + 4][col];
            }
            #pragma unroll
            for (int mt = 0; mt < 3; mt++) {
                unsigned a[4];
                int ar = wr + mt * 16 + qr;
                a[0] = As[ar][kk + qk];
                a[1] = As[ar + 8][kk + qk];
                a[2] = As[ar][kk + qk + 4];
                a[3] = As[ar + 8][kk + qk + 4];
                #pragma unroll
                for (int nt = 0; nt < 2; nt++) mma_tf32(acc[mt][nt], a, b[nt]);
            }
        }
    }
    #pragma unroll
    for (int mt = 0; mt < 3; mt++) {
        int r0 = rb + wr + mt * 16 + qr;
        #pragma unroll
        for (int nt = 0; nt < 2; nt++) {
            int c0 = wc + nt * 8 + 2 * qk;
            *(float2*)&g_y1[(size_t)r0 * MIDC + c0] = make_float2(acc[mt][nt][0], acc[mt][nt][1]);
            *(float2*)&g_y1[(size_t)(r0 + 8) * MIDC + c0] = make_float2(acc[mt][nt][2], acc[mt][nt][3]);
        }
    }
    #pragma unroll
    for (int nt = 0; nt < 2; nt++) {
        int c0 = wc + nt * 8 + 2 * qk;
        float se = 0.f, qe = 0.f, so = 0.f, qo = 0.f;
        #pragma unroll
        for (int mt = 0; mt < 3; mt++) {
            se += acc[mt][nt][0] + acc[mt][nt][2];
            qe += acc[mt][nt][0] * acc[mt][nt][0] + acc[mt][nt][2] * acc[mt][nt][2];
            so += acc[mt][nt][1] + acc[mt][nt][3];
            qo += acc[mt][nt][1] * acc[mt][nt][1] + acc[mt][nt][3] * acc[mt][nt][3];
        }
        atomicAdd(&s_sum[c0], se);     atomicAdd(&s_ss[c0], qe);
        atomicAdd(&s_sum[c0 + 1], so); atomicAdd(&s_ss[c0 + 1], qo);
    }
    __syncthreads();
    if (t < MIDC) {
        atomicAdd(&g_sum1[t], s_sum[t]);
        atomicAdd(&g_ss1[t], s_ss[t]);
    }
}

// ---------------- finalize BN1/BN2 params ----------------
__global__ void k_finalize(int which, const float* __restrict__ g, const float* __restrict__ b) {
    int c = threadIdx.x;
    if (c >= MIDC) return;
    const float* sum = which ? g_sum2 : g_sum1;
    const float* ss  = which ? g_ss2  : g_ss1;
    float* sc = which ? g_sc2 : g_sc1;
    float* sh = which ? g_sh2 : g_sh1;
    float m = sum[c] * (1.f / NP);
    float v = ss[c] * (1.f / NP) - m * m;
    float s = g[c] * rsqrtf(v + EPSV);
    sc[c] = s;
    sh[c] = b[c] - m * s;
}

// ---------------- einsum (TF32 mma + LDSM): h2 = sum_k relu(bn1(y1))[nbr[:,k]] @ W3[k] ---
// 128 threads, 4 warps: 2 row-groups(48) x 2 col-groups(32). B tile stored n-major.
__global__ void __launch_bounds__(128) k_einsum(const int* __restrict__ nbr) {
    __shared__ unsigned As[96][68];   // 96 rows x 64 k (stride 272 B)
    __shared__ unsigned Bs[64][72];   // 64 n-rows x 64 k (stride 288 B)
    __shared__ float s_sum[MIDC], s_ss[MIDC];

    int t = threadIdx.x;
    if (t < MIDC) { s_sum[t] = 0.f; s_ss[t] = 0.f; }

    int rb = blockIdx.x * 96;
    int lane = t & 31, w = t >> 5;
    int wr = (w & 1) * 48;
    int wc = (w >> 1) * 32;
    int f = t & 15;
    int rbase = t >> 4;
    int qr = lane >> 2, qk = lane & 3;

    float sc0 = g_sc1[4 * f + 0], sh0 = g_sh1[4 * f + 0];
    float sc1 = g_sc1[4 * f + 1], sh1 = g_sh1[4 * f + 1];
    float sc2 = g_sc1[4 * f + 2], sh2 = g_sh1[4 * f + 2];
    float sc3 = g_sc1[4 * f + 3], sh3 = g_sh1[4 * f + 3];

    const float4* y1v = (const float4*)g_y1;
    const uint4*  w3v = (const uint4*)g_W3t;

    // LDSM lane-base addresses
    uint32_t asBase = (uint32_t)__cvta_generic_to_shared(&As[0][0]);
    uint32_t bsBase = (uint32_t)__cvta_generic_to_shared(&Bs[0][0]);
    // A: lanes 0-15 -> rows wr+l, col kk; lanes 16-31 -> rows wr+(l-16), col kk+4
    uint32_t aAddr0 = asBase + (uint32_t)(wr + (lane & 15)) * 272u + (uint32_t)((lane >> 4) * 16);
    // B: rowB = wc + (l&7) + ((l>>4)<<3); colB 16B offset if (l>>3)&1
    uint32_t bAddr0 = bsBase + (uint32_t)(wc + (lane & 7) + ((lane >> 4) << 3)) * 288u
                             + (uint32_t)(((lane >> 3) & 1) * 16);

    float acc[3][4][4] = {};

    #pragma unroll 1
    for (int k = 0; k < KNB; k++) {
        __syncthreads();
        // B tile: W3[k] already n-major in g_W3t -> straight copy
        #pragma unroll
        for (int j = 0; j < 8; j++) {
            int c = rbase + 8 * j;
            uint4 v = w3v[((size_t)k * 64 + c) * 16 + f];
            *(uint4*)&Bs[c][4 * f] = v;
        }
        // A tile: gather + bn1 + relu + tf32
        #pragma unroll
        for (int j = 0; j < 12; j++) {
            int r = rbase + 8 * j;
            int src = nbr[(size_t)(rb + r) * KNB + k];
            float4 v = y1v[(size_t)src * 16 + f];
            As[r][4 * f + 0] = tf32_of(fmaxf(fmaf(v.x, sc0, sh0), 0.f));
            As[r][4 * f + 1] = tf32_of(fmaxf(fmaf(v.y, sc1, sh1), 0.f));
            As[r][4 * f + 2] = tf32_of(fmaxf(fmaf(v.z, sc2, sh2), 0.f));
            As[r][4 * f + 3] = tf32_of(fmaxf(fmaf(v.w, sc3, sh3), 0.f));
        }
        __syncthreads();
        #pragma unroll
        for (int kk = 0; kk < 64; kk += 8) {
            unsigned b[4][2];
            ldsm_x4(b[0][0], b[0][1], b[1][0], b[1][1], bAddr0 + kk * 4);
            ldsm_x4(b[2][0], b[2][1], b[3][0], b[3][1], bAddr0 + kk * 4 + 16u * 288u);
            #pragma unroll
            for (int mt = 0; mt < 3; mt++) {
                unsigned a[4];
                ldsm_x4(a[0], a[1], a[2], a[3], aAddr0 + kk * 4 + (uint32_t)mt * 16u * 272u);
                #pragma unroll
                for (int nt = 0; nt < 4; nt++) mma_tf32(acc[mt][nt], a, b[nt]);
            }
        }
    }
    #pragma unroll
    for (int mt = 0; mt < 3; mt++) {
        int r0 = rb + wr + mt * 16 + qr;
        #pragma unroll
        for (int nt = 0; nt < 4; nt++) {
            int c0 = wc + nt * 8 + 2 * qk;
            *(float2*)&g_h2[(size_t)r0 * MIDC + c0] = make_float2(acc[mt][nt][0], acc[mt][nt][1]);
            *(float2*)&g_h2[(size_t)(r0 + 8) * MIDC + c0] = make_float2(acc[mt][nt][2], acc[mt][nt][3]);
        }
    }
    #pragma unroll
    for (int nt = 0; nt < 4; nt++) {
        int c0 = wc + nt * 8 + 2 * qk;
        float se = 0.f, qe = 0.f, so = 0.f, qo = 0.f;
        #pragma unroll
        for (int mt = 0; mt < 3; mt++) {
            se += acc[mt][nt][0] + acc[mt][nt][2];
            qe += acc[mt][nt][0] * acc[mt][nt][0] + acc[mt][nt][2] * acc[mt][nt][2];
            so += acc[mt][nt][1] + acc[mt][nt][3];
            qo += acc[mt][nt][1] * acc[mt][nt][1] + acc[mt][nt][3] * acc[mt][nt][3];
        }
        atomicAdd(&s_sum[c0], se);     atomicAdd(&s_ss[c0], qe);
        atomicAdd(&s_sum[c0 + 1], so); atomicAdd(&s_ss[c0 + 1], qo);
    }
    __syncthreads();
    if (t < MIDC) {
        atomicAdd(&g_sum2[t], s_sum[t]);
        atomicAdd(&g_ss2[t], s_ss[t]);
    }
}

// ---------------- h = relu(bn2(h2)) -> tf32 bits; s += colsum(h); M += h^T h ------------
__global__ void __launch_bounds__(256) k_moment() {
    __shared__ float Hs[64][68];
    int t = threadIdx.x;
    int tx = t & 15, ty = t >> 4;
    size_t rb = (size_t)blockIdx.x * 64;
    for (int i = t; i < 64 * 64; i += 256) {
        int r = i >> 6, c = i & 63;
        float v = g_h2[(rb + r) * MIDC + c];
        float h = fmaxf(fmaf(v, g_sc2[c], g_sh2[c]), 0.f);
        Hs[r][c] = h;
        g_hbt[(rb + r) * MIDC + c] = tf32_of(h);
    }
    __syncthreads();
    if (t < 64) {
        float s = 0.f;
        #pragma unroll 8
        for (int r = 0; r < 64; r++) s += Hs[r][t];
        atomicAdd(&g_svec[t], s);
    }
    float acc[4][4] = {};
    #pragma unroll 8
    for (int r = 0; r < 64; r++) {
        float4 bv = *(const float4*)&Hs[r][4 * tx];
        float a0 = Hs[r][4 * ty + 0];
        float a1 = Hs[r][4 * ty + 1];
        float a2 = Hs[r][4 * ty + 2];
        float a3 = Hs[r][4 * ty + 3];
        acc[0][0] = fmaf(a0, bv.x, acc[0][0]); acc[0][1] = fmaf(a0, bv.y, acc[0][1]);
        acc[0][2] = fmaf(a0, bv.z, acc[0][2]); acc[0][3] = fmaf(a0, bv.w, acc[0][3]);
        acc[1][0] = fmaf(a1, bv.x, acc[1][0]); acc[1][1] = fmaf(a1, bv.y, acc[1][1]);
        acc[1][2] = fmaf(a1, bv.z, acc[1][2]); acc[1][3] = fmaf(a1, bv.w, acc[1][3]);
        acc[2][0] = fmaf(a2, bv.x, acc[2][0]); acc[2][1] = fmaf(a2, bv.y, acc[2][1]);
        acc[2][2] = fmaf(a2, bv.z, acc[2][2]); acc[2][3] = fmaf(a2, bv.w, acc[2][3]);
        acc[3][0] = fmaf(a3, bv.x, acc[3][0]); acc[3][1] = fmaf(a3, bv.y, acc[3][1]);
        acc[3][2] = fmaf(a3, bv.z, acc[3][2]); acc[3][3] = fmaf(a3, bv.w, acc[3][3]);
    }
    #pragma unroll
    for (int i = 0; i < 4; i++)
        #pragma unroll
        for (int j = 0; j < 4; j++)
            atomicAdd(&g_M[(4 * ty + i) * MIDC + 4 * tx + j], acc[i][j]);
}

// ---------------- BN3 params from s, M ----------------
__global__ void __launch_bounds__(256) k_finalize3(const float* __restrict__ W2,
                                                   const float* __restrict__ g3,
                                                   const float* __restrict__ b3) {
    __shared__ float Ms[64][65];
    __shared__ float sv[64];
    int t = threadIdx.x;
    for (int i = t; i < 64 * 64; i += 256) Ms[i >> 6][i & 63] = g_M[i] * (1.f / NP);
    if (t < 64) sv[t] = g_svec[t] * (1.f / NP);
    __syncthreads();

    int lane = t & 31, w = t >> 5;
    int c = blockIdx.x * 8 + w;
    float mean_p = 0.f, e2_p = 0.f;
    #pragma unroll
    for (int half = 0; half < 2; half++) {
        int bcol = lane + 32 * half;
        float wb = W2[(size_t)bcol * OUTC + c];
        mean_p = fmaf(sv[bcol], wb, mean_p);
        float p = 0.f;
        #pragma unroll 8
        for (int a = 0; a < 64; a++) {
            float wa = W2[(size_t)a * OUTC + c];
            p = fmaf(Ms[a][bcol], wa, p);
        }
        e2_p = fmaf(wb, p, e2_p);
    }
    #pragma unroll
    for (int off = 16; off > 0; off >>= 1) {
        mean_p += __shfl_xor_sync(0xFFFFFFFFu, mean_p, off);
        e2_p   += __shfl_xor_sync(0xFFFFFFFFu, e2_p, off);
    }
    if (lane == 0) {
        float var = e2_p - mean_p * mean_p;
        float s = g3[c] * rsqrtf(var + EPSV);
        g_sc3[c] = s;
        g_sh3[c] = b3[c] - mean_p * s;
    }
}

// ---------------- GEMM3 (TF32 mma) fused: out = relu(bn3(h @ W2) + x) ----------------
__global__ void __launch_bounds__(128) k_gemm3f(const float* __restrict__ x,
                                                float* __restrict__ out) {
    __shared__ unsigned As[96][68];
    __shared__ unsigned Bs[64][72];

    int t = threadIdx.x;
    int rb = blockIdx.x * 96;
    int cb = blockIdx.y * 64;
    int lane = t & 31, w = t >> 5;
    int wr = (w & 1) * 48;
    int wc = (w >> 1) * 32;
    int f = t & 15;
    int rbase = t >> 4;
    const uint4* hbv = (const uint4*)g_hbt;
    int qr = lane >> 2, qk = lane & 3;

    #pragma unroll
    for (int j = 0; j < 8; j++) {
        int c = rbase + 8 * j;
        uint4 v = *(const uint4*)&g_W2t[(size_t)c * OUTC + cb + 4 * f];
        *(uint4*)&Bs[c][4 * f] = v;
    }
    #pragma unroll
    for (int j = 0; j < 12; j++) {
        int r = rbase + 8 * j;
        uint4 v = hbv[(size_t)(rb + r) * 16 + f];
        *(uint4*)&As[r][4 * f] = v;
    }
    __syncthreads();

    float acc[3][4][4] = {};
    #pragma unroll
    for (int kk = 0; kk < 64; kk += 8) {
        unsigned b[4][2];
        #pragma unroll
        for (int nt = 0; nt < 4; nt++) {
            int col = wc + nt * 8 + qr;
            b[nt][0] = Bs[kk + qk][col];
            b[nt][1] = Bs[kk + qk + 4][col];
        }
        #pragma unroll
        for (int mt = 0; mt < 3; mt++) {
            unsigned a[4];
            int ar = wr + mt * 16 + qr;
            a[0] = As[ar][kk + qk];
            a[1] = As[ar + 8][kk + qk];
            a[2] = As[ar][kk + qk + 4];
            a[3] = As[ar + 8][kk + qk + 4];
            #pragma unroll
            for (int nt = 0; nt < 4; nt++) mma_tf32(acc[mt][nt], a, b[nt]);
        }
    }

    #pragma unroll
    for (int mt = 0; mt < 3; mt++) {
        int r0 = rb + wr + mt * 16 + qr;
        #pragma unroll
        for (int nt = 0; nt < 4; nt++) {
            int c0 = cb + wc + nt * 8 + 2 * qk;
            float sce = g_sc3[c0], she = g_sh3[c0];
            float sco = g_sc3[c0 + 1], sho = g_sh3[c0 + 1];
            float2 xa = *(const float2*)&x[(size_t)r0 * OUTC + c0];
            float2 xb = *(const float2*)&x[(size_t)(r0 + 8) * OUTC + c0];
            float2 oa, ob;
            oa.x = fmaxf(fmaf(acc[mt][nt][0], sce, she) + xa.x, 0.f);
            oa.y = fmaxf(fmaf(acc[mt][nt][1], sco, sho) + xa.y, 0.f);
            ob.x = fmaxf(fmaf(acc[mt][nt][2], sce, she) + xb.x, 0.f);
            ob.y = fmaxf(fmaf(acc[mt][nt][3], sco, sho) + xb.y, 0.f);
            *(float2*)&out[(size_t)r0 * OUTC + c0] = oa;
            *(float2*)&out[(size_t)(r0 + 8) * OUTC + c0] = ob;
        }
    }
}

// ---------------- host launch ----------------
extern "C" void kernel_launch(void* const* d_in, const int* in_sizes, int n_in,
                              void* d_out, int out_size) {
    const float* x    = (const float*)d_in[0];
    const int*   nbr  = (const int*)  d_in[1];
    const float* W1   = (const float*)d_in[2];
    const float* W3   = (const float*)d_in[3];
    const float* W2   = (const float*)d_in[4];
    const float* g1   = (const float*)d_in[5];
    const float* b1   = (const float*)d_in[6];
    const float* g2   = (const float*)d_in[7];
    const float* b2   = (const float*)d_in[8];
    const float* g3   = (const float*)d_in[9];
    const float* b3   = (const float*)d_in[10];
    float* out = (float*)d_out;

    k_zero<<<16, 256>>>();
    k_wcvt3<<<432, 256>>>(W3);
    k_wcvt2<<<64, 256>>>(W2);
    k_gemm1<<<NP / 96, 256>>>(x, W1);
    k_finalize<<<1, 64>>>(0, g1, b1);
    k_einsum<<<NP / 96, 128>>>(nbr);
    k_finalize<<<1, 64>>>(1, g2, b2);
    k_moment<<<NP / 64, 256>>>();
    k_finalize3<<<32, 256>>>(W2, g3, b3);
    k_gemm3f<<<dim3(NP / 96, 4), 128>>>(x, out);
}

// round 13
// speedup vs baseline: 1.1113x; 1.1113x over previous
#include <cuda_runtime.h>
#include <cuda_bf16.h>
#include <stdint.h>

#define NP   120000
#define INC  256
#define MIDC 64
#define OUTC 256
#define KNB  27
#define EPSV 1e-5f

// ---------------- scratch ----------------
__device__ float    g_y1[NP * MIDC];
__device__ float    g_h2[NP * MIDC];
__device__ unsigned g_hbt[NP * MIDC];
__device__ unsigned g_W3t[KNB * MIDC * MIDC];  // k-major (as in W3)
__device__ unsigned g_W2t[MIDC * OUTC];
__device__ float g_sum1[MIDC], g_ss1[MIDC], g_sc1[MIDC], g_sh1[MIDC];
__device__ float g_sum2[MIDC], g_ss2[MIDC], g_sc2[MIDC], g_sh2[MIDC];
__device__ float g_svec[MIDC];
__device__ float g_M[MIDC * MIDC];
__device__ float g_sc3[OUTC], g_sh3[OUTC];

__device__ __forceinline__ unsigned tf32_of(float f) {
    unsigned u;
    asm("cvt.rna.tf32.f32 %0, %1;" : "=r"(u) : "f"(f));
    return u;
}

__device__ __forceinline__ void mma_tf32(float* d, const unsigned* a, const unsigned* b) {
    asm volatile(
        "mma.sync.aligned.m16n8k8.row.col.f32.tf32.tf32.f32 "
        "{%0,%1,%2,%3}, {%4,%5,%6,%7}, {%8,%9}, {%0,%1,%2,%3};"
        : "+f"(d[0]), "+f"(d[1]), "+f"(d[2]), "+f"(d[3])
        : "r"(a[0]), "r"(a[1]), "r"(a[2]), "r"(a[3]), "r"(b[0]), "r"(b[1]));
}

// ---------------- zero accumulators ----------------
__global__ void k_zero() {
    int i = blockIdx.x * blockDim.x + threadIdx.x;
    if (i < MIDC) {
        g_sum1[i] = 0.f; g_ss1[i] = 0.f;
        g_sum2[i] = 0.f; g_ss2[i] = 0.f;
        g_svec[i] = 0.f;
    }
    if (i < MIDC * MIDC) g_M[i] = 0.f;
}

// ---------------- weight conversions ----------------
__global__ void k_wcvt3(const float* __restrict__ W3) {
    int i = blockIdx.x * blockDim.x + threadIdx.x;  // 432*256 exact
    g_W3t[i] = tf32_of(W3[i]);
}
__global__ void k_wcvt2(const float* __restrict__ W2) {
    int i = blockIdx.x * blockDim.x + threadIdx.x;  // 64*256 exact
    g_W2t[i] = tf32_of(W2[i]);
}

// ---------------- GEMM1 (TF32 mma, R7 geometry): y1 = x @ W1, fused BN1 stats ----------
// 256 threads, 8 warps: 2 row-groups(48) x 4 col-groups(16). Measured 70.8 us.
__global__ void __launch_bounds__(256) k_gemm1(const float* __restrict__ x,
                                               const float* __restrict__ W1) {
    __shared__ unsigned As[96][68];
    __shared__ unsigned Bs[64][72];
    __shared__ float s_sum[MIDC], s_ss[MIDC];

    int t = threadIdx.x;
    if (t < MIDC) { s_sum[t] = 0.f; s_ss[t] = 0.f; }

    int rb = blockIdx.x * 96;
    int lane = t & 31, w = t >> 5;
    int wr = (w & 1) * 48;
    int wc = (w >> 1) * 16;
    int f = t & 15;
    int rbase = t >> 4;
    int qr = lane >> 2, qk = lane & 3;

    float acc[3][2][4] = {};

    for (int k0 = 0; k0 < INC; k0 += 64) {
        __syncthreads();
        #pragma unroll
        for (int j = 0; j < 4; j++) {
            int c = rbase + 16 * j;
            float4 v = *(const float4*)&W1[(size_t)(k0 + c) * MIDC + 4 * f];
            Bs[c][4 * f + 0] = tf32_of(v.x);
            Bs[c][4 * f + 1] = tf32_of(v.y);
            Bs[c][4 * f + 2] = tf32_of(v.z);
            Bs[c][4 * f + 3] = tf32_of(v.w);
        }
        #pragma unroll
        for (int j = 0; j < 6; j++) {
            int r = rbase + 16 * j;
            float4 v = *(const float4*)&x[(size_t)(rb + r) * INC + k0 + 4 * f];
            As[r][4 * f + 0] = tf32_of(v.x);
            As[r][4 * f + 1] = tf32_of(v.y);
            As[r][4 * f + 2] = tf32_of(v.z);
            As[r][4 * f + 3] = tf32_of(v.w);
        }
        __syncthreads();
        #pragma unroll
        for (int kk = 0; kk < 64; kk += 8) {
            unsigned b[2][2];
            #pragma unroll
            for (int nt = 0; nt < 2; nt++) {
                int col = wc + nt * 8 + qr;
                b[nt][0] = Bs[kk + qk][col];
                b[nt][1] = Bs[kk + qk + 4][col];
            }
            #pragma unroll
            for (int mt = 0; mt < 3; mt++) {
                unsigned a[4];
                int ar = wr + mt * 16 + qr;
                a[0] = As[ar][kk + qk];
                a[1] = As[ar + 8][kk + qk];
                a[2] = As[ar][kk + qk + 4];
                a[3] = As[ar + 8][kk + qk + 4];
                #pragma unroll
                for (int nt = 0; nt < 2; nt++) mma_tf32(acc[mt][nt], a, b[nt]);
            }
        }
    }
    #pragma unroll
    for (int mt = 0; mt < 3; mt++) {
        int r0 = rb + wr + mt * 16 + qr;
        #pragma unroll
        for (int nt = 0; nt < 2; nt++) {
            int c0 = wc + nt * 8 + 2 * qk;
            *(float2*)&g_y1[(size_t)r0 * MIDC + c0] = make_float2(acc[mt][nt][0], acc[mt][nt][1]);
            *(float2*)&g_y1[(size_t)(r0 + 8) * MIDC + c0] = make_float2(acc[mt][nt][2], acc[mt][nt][3]);
        }
    }
    #pragma unroll
    for (int nt = 0; nt < 2; nt++) {
        int c0 = wc + nt * 8 + 2 * qk;
        float se = 0.f, qe = 0.f, so = 0.f, qo = 0.f;
        #pragma unroll
        for (int mt = 0; mt < 3; mt++) {
            se += acc[mt][nt][0] + acc[mt][nt][2];
            qe += acc[mt][nt][0] * acc[mt][nt][0] + acc[mt][nt][2] * acc[mt][nt][2];
            so += acc[mt][nt][1] + acc[mt][nt][3];
            qo += acc[mt][nt][1] * acc[mt][nt][1] + acc[mt][nt][3] * acc[mt][nt][3];
        }
        atomicAdd(&s_sum[c0], se);     atomicAdd(&s_ss[c0], qe);
        atomicAdd(&s_sum[c0 + 1], so); atomicAdd(&s_ss[c0 + 1], qo);
    }
    __syncthreads();
    if (t < MIDC) {
        atomicAdd(&g_sum1[t], s_sum[t]);
        atomicAdd(&g_ss1[t], s_ss[t]);
    }
}

// ---------------- finalize BN1/BN2 params ----------------
__global__ void k_finalize(int which, const float* __restrict__ g, const float* __restrict__ b) {
    int c = threadIdx.x;
    if (c >= MIDC) return;
    const float* sum = which ? g_sum2 : g_sum1;
    const float* ss  = which ? g_ss2  : g_ss1;
    float* sc = which ? g_sc2 : g_sc1;
    float* sh = which ? g_sh2 : g_sh1;
    float m = sum[c] * (1.f / NP);
    float v = ss[c] * (1.f / NP) - m * m;
    float s = g[c] * rsqrtf(v + EPSV);
    sc[c] = s;
    sh[c] = b[c] - m * s;
}

// ---------------- einsum (TF32 mma, R10 geometry): h2 = sum_k relu(bn1(y1))[nbr[:,k]] @ W3[k]
// 128 threads, 4 warps: 2 row-groups(48) x 2 col-groups(32). Plain LDS fragments.
__global__ void __launch_bounds__(128) k_einsum(const int* __restrict__ nbr) {
    __shared__ unsigned As[96][68];
    __shared__ unsigned Bs[64][72];
    __shared__ float s_sum[MIDC], s_ss[MIDC];

    int t = threadIdx.x;
    if (t < MIDC) { s_sum[t] = 0.f; s_ss[t] = 0.f; }

    int rb = blockIdx.x * 96;
    int lane = t & 31, w = t >> 5;
    int wr = (w & 1) * 48;
    int wc = (w >> 1) * 32;
    int f = t & 15;
    int rbase = t >> 4;
    int qr = lane >> 2, qk = lane & 3;

    float sc0 = g_sc1[4 * f + 0], sh0 = g_sh1[4 * f + 0];
    float sc1 = g_sc1[4 * f + 1], sh1 = g_sh1[4 * f + 1];
    float sc2 = g_sc1[4 * f + 2], sh2 = g_sh1[4 * f + 2];
    float sc3 = g_sc1[4 * f + 3], sh3 = g_sh1[4 * f + 3];

    const float4* y1v = (const float4*)g_y1;
    const uint4*  w3v = (const uint4*)g_W3t;

    float acc[3][4][4] = {};

    #pragma unroll 1
    for (int k = 0; k < KNB; k++) {
        __syncthreads();
        #pragma unroll
        for (int j = 0; j < 8; j++) {
            int c = rbase + 8 * j;
            uint4 v = w3v[((size_t)k * 64 + c) * 16 + f];
            *(uint4*)&Bs[c][4 * f] = v;
        }
        #pragma unroll
        for (int j = 0; j < 12; j++) {
            int r = rbase + 8 * j;
            int src = nbr[(size_t)(rb + r) * KNB + k];
            float4 v = y1v[(size_t)src * 16 + f];
            As[r][4 * f + 0] = tf32_of(fmaxf(fmaf(v.x, sc0, sh0), 0.f));
            As[r][4 * f + 1] = tf32_of(fmaxf(fmaf(v.y, sc1, sh1), 0.f));
            As[r][4 * f + 2] = tf32_of(fmaxf(fmaf(v.z, sc2, sh2), 0.f));
            As[r][4 * f + 3] = tf32_of(fmaxf(fmaf(v.w, sc3, sh3), 0.f));
        }
        __syncthreads();
        #pragma unroll
        for (int kk = 0; kk < 64; kk += 8) {
            unsigned b[4][2];
            #pragma unroll
            for (int nt = 0; nt < 4; nt++) {
                int col = wc + nt * 8 + qr;
                b[nt][0] = Bs[kk + qk][col];
                b[nt][1] = Bs[kk + qk + 4][col];
            }
            #pragma unroll
            for (int mt = 0; mt < 3; mt++) {
                unsigned a[4];
                int ar = wr + mt * 16 + qr;
                a[0] = As[ar][kk + qk];
                a[1] = As[ar + 8][kk + qk];
                a[2] = As[ar][kk + qk + 4];
                a[3] = As[ar + 8][kk + qk + 4];
                #pragma unroll
                for (int nt = 0; nt < 4; nt++) mma_tf32(acc[mt][nt], a, b[nt]);
            }
        }
    }
    #pragma unroll
    for (int mt = 0; mt < 3; mt++) {
        int r0 = rb + wr + mt * 16 + qr;
        #pragma unroll
        for (int nt = 0; nt < 4; nt++) {
            int c0 = wc + nt * 8 + 2 * qk;
            *(float2*)&g_h2[(size_t)r0 * MIDC + c0] = make_float2(acc[mt][nt][0], acc[mt][nt][1]);
            *(float2*)&g_h2[(size_t)(r0 + 8) * MIDC + c0] = make_float2(acc[mt][nt][2], acc[mt][nt][3]);
        }
    }
    #pragma unroll
    for (int nt = 0; nt < 4; nt++) {
        int c0 = wc + nt * 8 + 2 * qk;
        float se = 0.f, qe = 0.f, so = 0.f, qo = 0.f;
        #pragma unroll
        for (int mt = 0; mt < 3; mt++) {
            se += acc[mt][nt][0] + acc[mt][nt][2];
            qe += acc[mt][nt][0] * acc[mt][nt][0] + acc[mt][nt][2] * acc[mt][nt][2];
            so += acc[mt][nt][1] + acc[mt][nt][3];
            qo += acc[mt][nt][1] * acc[mt][nt][1] + acc[mt][nt][3] * acc[mt][nt][3];
        }
        atomicAdd(&s_sum[c0], se);     atomicAdd(&s_ss[c0], qe);
        atomicAdd(&s_sum[c0 + 1], so); atomicAdd(&s_ss[c0 + 1], qo);
    }
    __syncthreads();
    if (t < MIDC) {
        atomicAdd(&g_sum2[t], s_sum[t]);
        atomicAdd(&g_ss2[t], s_ss[t]);
    }
}

// ---------------- h = relu(bn2(h2)) -> tf32 bits; s += colsum(h); M += h^T h ------------
__global__ void __launch_bounds__(256) k_moment() {
    __shared__ float Hs[64][68];
    int t = threadIdx.x;
    int tx = t & 15, ty = t >> 4;
    size_t rb = (size_t)blockIdx.x * 64;
    for (int i = t; i < 64 * 64; i += 256) {
        int r = i >> 6, c = i & 63;
        float v = g_h2[(rb + r) * MIDC + c];
        float h = fmaxf(fmaf(v, g_sc2[c], g_sh2[c]), 0.f);
        Hs[r][c] = h;
        g_hbt[(rb + r) * MIDC + c] = tf32_of(h);
    }
    __syncthreads();
    if (t < 64) {
        float s = 0.f;
        #pragma unroll 8
        for (int r = 0; r < 64; r++) s += Hs[r][t];
        atomicAdd(&g_svec[t], s);
    }
    float acc[4][4] = {};
    #pragma unroll 8
    for (int r = 0; r < 64; r++) {
        float4 bv = *(const float4*)&Hs[r][4 * tx];
        float a0 = Hs[r][4 * ty + 0];
        float a1 = Hs[r][4 * ty + 1];
        float a2 = Hs[r][4 * ty + 2];
        float a3 = Hs[r][4 * ty + 3];
        acc[0][0] = fmaf(a0, bv.x, acc[0][0]); acc[0][1] = fmaf(a0, bv.y, acc[0][1]);
        acc[0][2] = fmaf(a0, bv.z, acc[0][2]); acc[0][3] = fmaf(a0, bv.w, acc[0][3]);
        acc[1][0] = fmaf(a1, bv.x, acc[1][0]); acc[1][1] = fmaf(a1, bv.y, acc[1][1]);
        acc[1][2] = fmaf(a1, bv.z, acc[1][2]); acc[1][3] = fmaf(a1, bv.w, acc[1][3]);
        acc[2][0] = fmaf(a2, bv.x, acc[2][0]); acc[2][1] = fmaf(a2, bv.y, acc[2][1]);
        acc[2][2] = fmaf(a2, bv.z, acc[2][2]); acc[2][3] = fmaf(a2, bv.w, acc[2][3]);
        acc[3][0] = fmaf(a3, bv.x, acc[3][0]); acc[3][1] = fmaf(a3, bv.y, acc[3][1]);
        acc[3][2] = fmaf(a3, bv.z, acc[3][2]); acc[3][3] = fmaf(a3, bv.w, acc[3][3]);
    }
    #pragma unroll
    for (int i = 0; i < 4; i++)
        #pragma unroll
        for (int j = 0; j < 4; j++)
            atomicAdd(&g_M[(4 * ty + i) * MIDC + 4 * tx + j], acc[i][j]);
}

// ---------------- BN3 params from s, M ----------------
__global__ void __launch_bounds__(256) k_finalize3(const float* __restrict__ W2,
                                                   const float* __restrict__ g3,
                                                   const float* __restrict__ b3) {
    __shared__ float Ms[64][65];
    __shared__ float sv[64];
    int t = threadIdx.x;
    for (int i = t; i < 64 * 64; i += 256) Ms[i >> 6][i & 63] = g_M[i] * (1.f / NP);
    if (t < 64) sv[t] = g_svec[t] * (1.f / NP);
    __syncthreads();

    int lane = t & 31, w = t >> 5;
    int c = blockIdx.x * 8 + w;
    float mean_p = 0.f, e2_p = 0.f;
    #pragma unroll
    for (int half = 0; half < 2; half++) {
        int bcol = lane + 32 * half;
        float wb = W2[(size_t)bcol * OUTC + c];
        mean_p = fmaf(sv[bcol], wb, mean_p);
        float p = 0.f;
        #pragma unroll 8
        for (int a = 0; a < 64; a++) {
            float wa = W2[(size_t)a * OUTC + c];
            p = fmaf(Ms[a][bcol], wa, p);
        }
        e2_p = fmaf(wb, p, e2_p);
    }
    #pragma unroll
    for (int off = 16; off > 0; off >>= 1) {
        mean_p += __shfl_xor_sync(0xFFFFFFFFu, mean_p, off);
        e2_p   += __shfl_xor_sync(0xFFFFFFFFu, e2_p, off);
    }
    if (lane == 0) {
        float var = e2_p - mean_p * mean_p;
        float s = g3[c] * rsqrtf(var + EPSV);
        g_sc3[c] = s;
        g_sh3[c] = b3[c] - mean_p * s;
    }
}

// ---------------- GEMM3 (TF32 mma, R10 geometry) fused: out = relu(bn3(h @ W2) + x) ------
__global__ void __launch_bounds__(128) k_gemm3f(const float* __restrict__ x,
                                                float* __restrict__ out) {
    __shared__ unsigned As[96][68];
    __shared__ unsigned Bs[64][72];

    int t = threadIdx.x;
    int rb = blockIdx.x * 96;
    int cb = blockIdx.y * 64;
    int lane = t & 31, w = t >> 5;
    int wr = (w & 1) * 48;
    int wc = (w >> 1) * 32;
    int f = t & 15;
    int rbase = t >> 4;
    const uint4* hbv = (const uint4*)g_hbt;
    int qr = lane >> 2, qk = lane & 3;

    #pragma unroll
    for (int j = 0; j < 8; j++) {
        int c = rbase + 8 * j;
        uint4 v = *(const uint4*)&g_W2t[(size_t)c * OUTC + cb + 4 * f];
        *(uint4*)&Bs[c][4 * f] = v;
    }
    #pragma unroll
    for (int j = 0; j < 12; j++) {
        int r = rbase + 8 * j;
        uint4 v = hbv[(size_t)(rb + r) * 16 + f];
        *(uint4*)&As[r][4 * f] = v;
    }
    __syncthreads();

    float acc[3][4][4] = {};
    #pragma unroll
    for (int kk = 0; kk < 64; kk += 8) {
        unsigned b[4][2];
        #pragma unroll
        for (int nt = 0; nt < 4; nt++) {
            int col = wc + nt * 8 + qr;
            b[nt][0] = Bs[kk + qk][col];
            b[nt][1] = Bs[kk + qk + 4][col];
        }
        #pragma unroll
        for (int mt = 0; mt < 3; mt++) {
            unsigned a[4];
            int ar = wr + mt * 16 + qr;
            a[0] = As[ar][kk + qk];
            a[1] = As[ar + 8][kk + qk];
            a[2] = As[ar][kk + qk + 4];
            a[3] = As[ar + 8][kk + qk + 4];
            #pragma unroll
            for (int nt = 0; nt < 4; nt++) mma_tf32(acc[mt][nt], a, b[nt]);
        }
    }

    #pragma unroll
    for (int mt = 0; mt < 3; mt++) {
        int r0 = rb + wr + mt * 16 + qr;
        #pragma unroll
        for (int nt = 0; nt < 4; nt++) {
            int c0 = cb + wc + nt * 8 + 2 * qk;
            float sce = g_sc3[c0], she = g_sh3[c0];
            float sco = g_sc3[c0 + 1], sho = g_sh3[c0 + 1];
            float2 xa = *(const float2*)&x[(size_t)r0 * OUTC + c0];
            float2 xb = *(const float2*)&x[(size_t)(r0 + 8) * OUTC + c0];
            float2 oa, ob;
            oa.x = fmaxf(fmaf(acc[mt][nt][0], sce, she) + xa.x, 0.f);
            oa.y = fmaxf(fmaf(acc[mt][nt][1], sco, sho) + xa.y, 0.f);
            ob.x = fmaxf(fmaf(acc[mt][nt][2], sce, she) + xb.x, 0.f);
            ob.y = fmaxf(fmaf(acc[mt][nt][3], sco, sho) + xb.y, 0.f);
            *(float2*)&out[(size_t)r0 * OUTC + c0] = oa;
            *(float2*)&out[(size_t)(r0 + 8) * OUTC + c0] = ob;
        }
    }
}

// ---------------- host launch ----------------
extern "C" void kernel_launch(void* const* d_in, const int* in_sizes, int n_in,
                              void* d_out, int out_size) {
    const float* x    = (const float*)d_in[0];
    const int*   nbr  = (const int*)  d_in[1];
    const float* W1   = (const float*)d_in[2];
    const float* W3   = (const float*)d_in[3];
    const float* W2   = (const float*)d_in[4];
    const float* g1   = (const float*)d_in[5];
    const float* b1   = (const float*)d_in[6];
    const float* g2   = (const float*)d_in[7];
    const float* b2   = (const float*)d_in[8];
    const float* g3   = (const float*)d_in[9];
    const float* b3   = (const float*)d_in[10];
    float* out = (float*)d_out;

    k_zero<<<16, 256>>>();
    k_wcvt3<<<432, 256>>>(W3);
    k_wcvt2<<<64, 256>>>(W2);
    k_gemm1<<<NP / 96, 256>>>(x, W1);
    k_finalize<<<1, 64>>>(0, g1, b1);
    k_einsum<<<NP / 96, 128>>>(nbr);
    k_finalize<<<1, 64>>>(1, g2, b2);
    k_moment<<<NP / 64, 256>>>();
    k_finalize3<<<32, 256>>>(W2, g3, b3);
    k_gemm3f<<<dim3(NP / 96, 4), 128>>>(x, out);
}